// round 6
// baseline (speedup 1.0000x reference)
#include <cuda_runtime.h>

#define B_   4
#define CIN  256
#define CO   128
#define HI   64
#define WI   64
#define HO   128
#define WO   128

typedef unsigned long long u64t;

// Scratch: intermediate y, pre-transposed weights.
__device__ float g_y[B_ * CO * HO * WO];            // 32 MB
__device__ float g_w1t[4 * CIN * 4 * CO];           // [parity][c][tap][o]
__device__ float g_w2t[CO * 9 * CO];                // [c][tap][o]

// ---- packed f32x2 helpers -------------------------------------------------
__device__ __forceinline__ void ffma2(u64t& d, u64t a, u64t b) {
    asm("fma.rn.f32x2 %0, %1, %2, %0;" : "+l"(d) : "l"(a), "l"(b));
}
__device__ __forceinline__ u64t bcast2(float v) {
    u64t r;
    asm("mov.b64 %0, {%1, %1};" : "=l"(r) : "f"(v));
    return r;
}
__device__ __forceinline__ void unpack2(float& lo, float& hi, u64t p) {
    asm("mov.b64 {%0, %1}, %2;" : "=f"(lo), "=f"(hi) : "l"(p));
}

// ---------------------------------------------------------------------------
// Weight pre-transpose kernels
// ---------------------------------------------------------------------------
__global__ void prep_w1_kernel(const float* __restrict__ w1) {
    int idx = blockIdx.x * blockDim.x + threadIdx.x;
    const int total = 4 * CIN * 4 * CO;
    for (; idx < total; idx += gridDim.x * blockDim.x) {
        int o   = idx & 127;
        int tap = (idx >> 7) & 3;
        int c   = (idx >> 9) & 255;
        int par = idx >> 17;
        int ph = par >> 1, pw = par & 1;
        int a  = tap >> 1, bb = tap & 1;
        int kh = 2 * a + 1 - ph;
        int kw = 2 * bb + 1 - pw;
        g_w1t[idx] = w1[((c * CO + o) * 4 + kh) * 4 + kw];
    }
}

__global__ void prep_w2_kernel(const float* __restrict__ w2) {
    int idx = blockIdx.x * blockDim.x + threadIdx.x;
    const int total = CO * 9 * CO;
    for (; idx < total; idx += gridDim.x * blockDim.x) {
        int c   = idx / 1152;
        int rem = idx - c * 1152;
        int tap = rem >> 7;
        int o   = rem & 127;
        int i = tap / 3, j = tap % 3;
        g_w2t[idx] = w2[(c * CO + o) * 9 + (2 - i) * 3 + (2 - j)];
    }
}

// ---------------------------------------------------------------------------
// Stage 1: conv_transpose 4x4 s2 p1, 4 subpixel parities, FFMA2 over o-pairs.
// ---------------------------------------------------------------------------
__global__ __launch_bounds__(256) void deconv_kernel(const float* __restrict__ x,
                                                     const float* __restrict__ b1) {
    __shared__ float xs[8 * 9 * 17];    // [c][r*17+s], pitch 17
    __shared__ float ws[8 * 4 * 128];   // [c][tap][o]

    const int tid  = threadIdx.x;
    const int bz   = blockIdx.z;
    const int bimg = bz >> 2;
    const int par  = bz & 3;
    const int ph = par >> 1, pw = par & 1;
    const int th0 = blockIdx.y * 8;
    const int tw0 = blockIdx.x * 16;

    const int og8   = (tid >> 4) * 8;
    const int pg    = tid & 15;
    const int prow  = pg >> 1;
    const int pcol8 = (pg & 1) * 8;

    const int base_h = th0 - 1 + ph;
    const int base_w = tw0 - 1 + pw;

    const float* wsrc = g_w1t + par * (CIN * 4 * CO);
    const float* xsrc = x + bimg * (CIN * HI * WI);

    u64t accp[4][8];
#pragma unroll
    for (int a = 0; a < 4; ++a)
#pragma unroll
        for (int b = 0; b < 8; ++b) accp[a][b] = 0ull;

    for (int c0 = 0; c0 < CIN; c0 += 8) {
        {
            const float4* src = (const float4*)(wsrc + c0 * 512);
            float4* dst = (float4*)ws;
            for (int e = tid; e < 1024; e += 256) dst[e] = src[e];
        }
        for (int e = tid; e < 8 * 153; e += 256) {
            int c = e / 153;
            int rem = e - c * 153;
            int r = rem / 17, s = rem - r * 17;
            int ih = base_h + r, iw = base_w + s;
            float v = 0.f;
            if ((unsigned)ih < 64u && (unsigned)iw < 64u)
                v = xsrc[((c0 + c) * HI + ih) * WI + iw];
            xs[e] = v;
        }
        __syncthreads();

#pragma unroll
        for (int tap = 0; tap < 4; ++tap) {
            const int a  = tap >> 1;
            const int bb = tap & 1;
#pragma unroll
            for (int c = 0; c < 8; ++c) {
                const float* wrow = ws + (c * 4 + tap) * 128 + og8;
                u64t wp[4];
#pragma unroll
                for (int p = 0; p < 4; ++p)
                    wp[p] = *(const u64t*)(wrow + 2 * p);
                const float* xrow = xs + c * 153 + (prow + 1 - a) * 17 + (pcol8 + 1 - bb);
                u64t xb[8];
#pragma unroll
                for (int jj = 0; jj < 8; ++jj) xb[jj] = bcast2(xrow[jj]);
#pragma unroll
                for (int p = 0; p < 4; ++p)
#pragma unroll
                    for (int jj = 0; jj < 8; ++jj)
                        ffma2(accp[p][jj], wp[p], xb[jj]);
            }
        }
        __syncthreads();
    }

    const int oh = 2 * (th0 + prow) + ph;
#pragma unroll
    for (int p = 0; p < 4; ++p) {
        int o = og8 + 2 * p;
        float bias0 = __ldg(&b1[o]);
        float bias1 = __ldg(&b1[o + 1]);
        float* y0 = g_y + ((bimg * CO + o) * HO + oh) * WO;
        float* y1 = y0 + HO * WO;
#pragma unroll
        for (int jj = 0; jj < 8; ++jj) {
            int ow = 2 * (tw0 + pcol8 + jj) + pw;
            float lo, hi;
            unpack2(lo, hi, accp[p][jj]);
            y0[ow] = lo + bias0;
            y1[ow] = hi + bias1;
        }
    }
}

// ---------------------------------------------------------------------------
// Stage 2: PAC conv_transpose 3x3 s1 p1, FFMA2 over o-pairs.
// ---------------------------------------------------------------------------
__global__ __launch_bounds__(256) void pac_kernel(const float* __restrict__ guide,
                                                  const float* __restrict__ b2,
                                                  float* __restrict__ out) {
    __shared__ float tile[8 * 190];     // [c][r*19+s], pitch 19
    __shared__ float ksm[9 * 128];      // [tap][px]
    __shared__ float wt[8 * 9 * 128];   // [c][tap][o]

    const int tid  = threadIdx.x;
    const int bimg = blockIdx.z;
    const int h0   = blockIdx.y * 8;
    const int w0   = blockIdx.x * 16;

    const int og8   = (tid >> 4) * 8;
    const int pg    = tid & 15;
    const int prow  = pg >> 1;
    const int pcol8 = (pg & 1) * 8;

    const float* gsrc = guide + bimg * (CO * HO * WO);
    const float* ysrc = g_y   + bimg * (CO * HO * WO);

    // ---- Phase A: Gaussian kernel weights ----
    float ssd[5] = {0.f, 0.f, 0.f, 0.f, 0.f};
    for (int c0 = 0; c0 < CO; c0 += 8) {
        for (int e = tid; e < 8 * 190; e += 256) {
            int c = e / 190;
            int rem = e - c * 190;
            int r = rem / 19, s = rem - r * 19;
            int gh = h0 - 1 + r, gw = w0 - 1 + s;
            float v = 0.f;
            if ((unsigned)gh < 128u && (unsigned)gw < 128u)
                v = gsrc[((c0 + c) * HO + gh) * WO + gw];
            tile[e] = v;
        }
        __syncthreads();
#pragma unroll
        for (int t = 0; t < 5; ++t) {
            int task = tid + t * 256;
            if (task < 1152) {
                int tap = task >> 7;
                int px  = task & 127;
                int i = tap / 3, j = tap - i * 3;
                int pr = px >> 4, pc = px & 15;
                float s_ = ssd[t];
#pragma unroll
                for (int c = 0; c < 8; ++c) {
                    float ctr = tile[c * 190 + (pr + 1) * 19 + pc + 1];
                    float nb  = tile[c * 190 + (pr + i) * 19 + pc + j];
                    float d = nb - ctr;
                    s_ = fmaf(d, d, s_);
                }
                ssd[t] = s_;
            }
        }
        __syncthreads();
    }
#pragma unroll
    for (int t = 0; t < 5; ++t) {
        int task = tid + t * 256;
        if (task < 1152) ksm[task] = __expf(-0.5f * ssd[t]);
    }
    __syncthreads();

    // ---- Phase B: main GEMM ----
    u64t accp[4][8];
#pragma unroll
    for (int a = 0; a < 4; ++a)
#pragma unroll
        for (int b = 0; b < 8; ++b) accp[a][b] = 0ull;

    for (int c0 = 0; c0 < CO; c0 += 8) {
        for (int e = tid; e < 8 * 190; e += 256) {
            int c = e / 190;
            int rem = e - c * 190;
            int r = rem / 19, s = rem - r * 19;
            int yh = h0 - 1 + r, yw = w0 - 1 + s;
            float v = 0.f;
            if ((unsigned)yh < 128u && (unsigned)yw < 128u)
                v = ysrc[((c0 + c) * HO + yh) * WO + yw];
            tile[e] = v;
        }
        {
            const float4* src = (const float4*)(g_w2t + c0 * 1152);
            float4* dst = (float4*)wt;
            for (int e = tid; e < 2304; e += 256) dst[e] = src[e];
        }
        __syncthreads();

#pragma unroll 1
        for (int tap = 0; tap < 9; ++tap) {
            const int i = tap / 3, j = tap - i * 3;
            float kv[8];
#pragma unroll
            for (int jj = 0; jj < 8; ++jj)
                kv[jj] = ksm[tap * 128 + prow * 16 + pcol8 + jj];
#pragma unroll
            for (int c = 0; c < 8; ++c) {
                const float* wrow = wt + (c * 9 + tap) * 128 + og8;
                u64t wp[4];
#pragma unroll
                for (int p = 0; p < 4; ++p)
                    wp[p] = *(const u64t*)(wrow + 2 * p);
                const float* yrow = tile + c * 190 + (prow + i) * 19 + (pcol8 + j);
                u64t ykp[8];
#pragma unroll
                for (int jj = 0; jj < 8; ++jj)
                    ykp[jj] = bcast2(yrow[jj] * kv[jj]);
#pragma unroll
                for (int p = 0; p < 4; ++p)
#pragma unroll
                    for (int jj = 0; jj < 8; ++jj)
                        ffma2(accp[p][jj], wp[p], ykp[jj]);
            }
        }
        __syncthreads();
    }

    const int h = h0 + prow;
#pragma unroll
    for (int p = 0; p < 4; ++p) {
        int o = og8 + 2 * p;
        float bias0 = __ldg(&b2[o]);
        float bias1 = __ldg(&b2[o + 1]);
        float* dst0 = out + ((bimg * CO + o) * HO + h) * WO + w0 + pcol8;
        float* dst1 = dst0 + HO * WO;
#pragma unroll
        for (int jj = 0; jj < 8; ++jj) {
            float lo, hi;
            unpack2(lo, hi, accp[p][jj]);
            dst0[jj] = lo + bias0;
            dst1[jj] = hi + bias1;
        }
    }
}

// ---------------------------------------------------------------------------
extern "C" void kernel_launch(void* const* d_in, const int* in_sizes, int n_in,
                              void* d_out, int out_size) {
    const float* x     = (const float*)d_in[0];
    const float* guide = (const float*)d_in[1];
    const float* w1    = (const float*)d_in[2];
    const float* b1    = (const float*)d_in[3];
    const float* w2    = (const float*)d_in[4];
    const float* b2    = (const float*)d_in[5];
    float* out = (float*)d_out;

    prep_w1_kernel<<<512, 256>>>(w1);
    prep_w2_kernel<<<288, 256>>>(w2);
    deconv_kernel<<<dim3(4, 8, 16), 256>>>(x, b1);
    pac_kernel<<<dim3(8, 16, 4), 256>>>(guide, b2, out);
}

// round 10
// speedup vs baseline: 1.6852x; 1.6852x over previous
#include <cuda_runtime.h>
#include <mma.h>
#include <cstdint>

using namespace nvcuda;

#define B_   4
#define CIN  256
#define CO   128
#define HI   64
#define WI   64
#define HO   128
#define WO   128

// Scratch buffers
__device__ float g_y[B_ * CO * HO * WO];      // deconv output (incl. bias)
__device__ float g_k[B_ * 9 * HO * WO];       // gaussian PAC weights
__device__ float g_w1a[4 * 33 * CO * 32];     // [par][chunk][o][kk], tf32; chunk32=bias
__device__ float g_w2a[37 * CO * 32];         // [chunk][o][kk], tf32; chunk36=bias

__device__ __forceinline__ float tf32r(float v) {
    float r;
    asm("cvt.rna.tf32.f32 %0, %1;" : "=f"(r) : "f"(v));
    return r;
}

// ===================== Weight prep =====================
__global__ void prep_w1a_kernel(const float* __restrict__ w1,
                                const float* __restrict__ b1) {
    int idx = blockIdx.x * blockDim.x + threadIdx.x;
    const int total = 4 * 33 * CO * 32;
    for (; idx < total; idx += gridDim.x * blockDim.x) {
        int kk    = idx & 31;
        int o     = (idx >> 5) & 127;
        int rem   = idx >> 12;          // par*33 + chunk
        int par   = rem / 33;
        int chunk = rem - par * 33;
        float v;
        if (chunk == 32) {
            v = (kk == 0) ? b1[o] : 0.f;
        } else {
            int cc = chunk >> 2, tap = chunk & 3;
            int c  = cc * 32 + kk;
            int ph = par >> 1, pw = par & 1;
            int a  = tap >> 1, bb = tap & 1;
            int kh = 2 * a + 1 - ph;
            int kw = 2 * bb + 1 - pw;
            v = w1[((c * CO + o) * 4 + kh) * 4 + kw];
        }
        g_w1a[idx] = tf32r(v);
    }
}

__global__ void prep_w2a_kernel(const float* __restrict__ w2,
                                const float* __restrict__ b2) {
    int idx = blockIdx.x * blockDim.x + threadIdx.x;
    const int total = 37 * CO * 32;
    for (; idx < total; idx += gridDim.x * blockDim.x) {
        int kk    = idx & 31;
        int o     = (idx >> 5) & 127;
        int chunk = idx >> 12;
        float v;
        if (chunk == 36) {
            v = (kk == 0) ? b2[o] : 0.f;
        } else {
            int cc = chunk / 9, tap = chunk - cc * 9;
            int c  = cc * 32 + kk;
            int i = tap / 3, j = tap - i * 3;
            v = w2[(c * CO + o) * 9 + (2 - i) * 3 + (2 - j)];
        }
        g_w2a[idx] = tf32r(v);
    }
}

// ===================== Gaussian kernel weights ==========
__global__ __launch_bounds__(256) void gauss_kernel(const float* __restrict__ guide) {
    __shared__ float gs[8 * 342];   // [c][r*19+s], pitch 19, 18 rows

    const int tid  = threadIdx.x;
    const int bimg = blockIdx.z;
    const int h0   = blockIdx.y * 16;
    const int w0   = blockIdx.x * 16;
    const int pr = tid >> 4, pc = tid & 15;

    const float* gsrc = guide + bimg * (CO * HO * WO);

    float ssd[9];
#pragma unroll
    for (int t = 0; t < 9; ++t) ssd[t] = 0.f;

    for (int c0 = 0; c0 < CO; c0 += 8) {
        for (int e = tid; e < 8 * 342; e += 256) {
            int c = e / 342;
            int rem = e - c * 342;
            int r = rem / 19, s = rem - r * 19;
            int gh = h0 - 1 + r, gw = w0 - 1 + s;
            float v = 0.f;
            if ((unsigned)gh < 128u && (unsigned)gw < 128u)
                v = gsrc[((c0 + c) * HO + gh) * WO + gw];
            gs[e] = v;
        }
        __syncthreads();
#pragma unroll
        for (int t = 0; t < 9; ++t) {
            const int ti = t / 3, tj = t - ti * 3;
            float s_ = ssd[t];
#pragma unroll
            for (int c = 0; c < 8; ++c) {
                float ctr = gs[c * 342 + (pr + 1) * 19 + (pc + 1)];
                float nb  = gs[c * 342 + (pr + ti) * 19 + (pc + tj)];
                float d = nb - ctr;
                s_ = fmaf(d, d, s_);
            }
            ssd[t] = s_;
        }
        __syncthreads();
    }
#pragma unroll
    for (int t = 0; t < 9; ++t)
        g_k[((bimg * 9 + t) * HO + h0 + pr) * WO + w0 + pc] = __expf(-0.5f * ssd[t]);
}

// ===================== WMMA GEMM fragments ==============
typedef wmma::fragment<wmma::matrix_a, 16, 16, 8, wmma::precision::tf32, wmma::row_major> FragA;
typedef wmma::fragment<wmma::matrix_b, 16, 16, 8, wmma::precision::tf32, wmma::row_major> FragB;
typedef wmma::fragment<wmma::accumulator, 16, 16, 8, float> FragC;

// smem byte offsets (shared by both GEMM kernels)
#define OFF_XS 0            // 32*342 floats = 43776 B (input halo)
#define OFF_BS 43776        // 32*260 floats = 33280 B (B tile, pitch 260)
#define OFF_AS 77056        // 64*36  floats =  9216 B (A tile, pitch 36)
#define SMEM_DC 86272
#define OFF_KG 86272        // pac only: 9*256 floats = 9216 B
#define SMEM_PAC 95488
#define CS_PITCH 264        // deconv epilogue staging (reuses OFF_XS region)

// ===================== Stage 1: deconv via WMMA tf32 =====================
__global__ __launch_bounds__(256) void deconv_wmma(const float* __restrict__ x) {
    extern __shared__ char smem[];
    float* xs = (float*)(smem + OFF_XS);
    float* Bs = (float*)(smem + OFF_BS);
    float* As = (float*)(smem + OFF_AS);

    const int tid  = threadIdx.x;
    const int wid  = tid >> 5;
    const int bz   = blockIdx.z;
    const int bimg = bz >> 3;
    const int par  = (bz >> 1) & 3;
    const int half = bz & 1;
    const int ph = par >> 1, pw = par & 1;
    const int th0 = blockIdx.y * 16;   // parity-grid coords (0..63)
    const int tw0 = blockIdx.x * 16;
    const int pr = tid >> 4, pc = tid & 15;

    const int warp_m = wid >> 2;       // 0..1 -> rows warp_m*32
    const int warp_n = wid & 3;        // 0..3 -> cols warp_n*64

    const int base_h = th0 - 1 + ph;
    const int base_w = tw0 - 1 + pw;
    const float* xsrc = x + bimg * (CIN * HI * WI);
    const float* wbase = g_w1a + par * (33 * CO * 32);

    FragC cf[2][4];
#pragma unroll
    for (int i = 0; i < 2; ++i)
#pragma unroll
        for (int j = 0; j < 4; ++j) wmma::fill_fragment(cf[i][j], 0.f);

    for (int cc = 0; cc < 9; ++cc) {          // 8 c-blocks + 1 bias pass
        const bool bias_pass = (cc == 8);
        if (!bias_pass) {
            for (int e = tid; e < 32 * 342; e += 256) {
                int c = e / 342;
                int rem = e - c * 342;
                int r = rem / 19, s = rem - r * 19;
                int ih = base_h + r, iw = base_w + s;
                float v = 0.f;
                if ((unsigned)ih < 64u && (unsigned)iw < 64u)
                    v = xsrc[((cc * 32 + c) * HI + ih) * WI + iw];
                xs[e] = v;
            }
        }
        __syncthreads();

        const int ntap = bias_pass ? 1 : 4;
        for (int tap = 0; tap < ntap; ++tap) {
            const int chunk = bias_pass ? 32 : cc * 4 + tap;
            // A tile: 64 x 32, pitch 36
            {
                const float4* asrc = (const float4*)(wbase + (chunk * CO + half * 64) * 32);
#pragma unroll
                for (int q = 0; q < 2; ++q) {
                    int idx = tid + q * 256;          // 0..511
                    int row = idx >> 3, kb = idx & 7;
                    *(float4*)(As + row * 36 + kb * 4) = asrc[idx];
                }
            }
            // B tile: 32 x 256, pitch 260; thread owns column px=tid
            if (bias_pass) {
#pragma unroll
                for (int kk = 0; kk < 32; ++kk)
                    Bs[kk * 260 + tid] = (kk == 0) ? 1.f : 0.f;
            } else {
                const int a = tap >> 1, bb = tap & 1;
                const float* xb = xs + (pr + 1 - a) * 19 + (pc + 1 - bb);
#pragma unroll
                for (int kk = 0; kk < 32; ++kk)
                    Bs[kk * 260 + tid] = tf32r(xb[kk * 342]);
            }
            __syncthreads();

#pragma unroll
            for (int ks = 0; ks < 4; ++ks) {
                FragA af[2];
                FragB bf[4];
#pragma unroll
                for (int i = 0; i < 2; ++i)
                    wmma::load_matrix_sync(af[i], As + (warp_m * 32 + i * 16) * 36 + ks * 8, 36);
#pragma unroll
                for (int j = 0; j < 4; ++j)
                    wmma::load_matrix_sync(bf[j], Bs + ks * 8 * 260 + warp_n * 64 + j * 16, 260);
#pragma unroll
                for (int i = 0; i < 2; ++i)
#pragma unroll
                    for (int j = 0; j < 4; ++j)
                        wmma::mma_sync(cf[i][j], af[i], bf[j], cf[i][j]);
            }
            __syncthreads();
        }
    }

    // Epilogue: stage to smem, then stride-2 scatter to g_y
    float* Cs = (float*)(smem);   // 64 x 264 floats, reuses xs+Bs
#pragma unroll
    for (int i = 0; i < 2; ++i)
#pragma unroll
        for (int j = 0; j < 4; ++j)
            wmma::store_matrix_sync(Cs + (warp_m * 32 + i * 16) * CS_PITCH + warp_n * 64 + j * 16,
                                    cf[i][j], CS_PITCH, wmma::mem_row_major);
    __syncthreads();

    const int oh = 2 * (th0 + pr) + ph;
    const int ow = 2 * (tw0 + pc) + pw;
    float* ydst = g_y + ((bimg * CO + half * 64) * HO + oh) * WO + ow;
#pragma unroll 4
    for (int o = 0; o < 64; ++o)
        ydst[o * HO * WO] = Cs[o * CS_PITCH + tid];
}

// ===================== Stage 2: PAC via WMMA tf32 =====================
__global__ __launch_bounds__(256) void pac_wmma(float* __restrict__ out) {
    extern __shared__ char smem[];
    float* ys = (float*)(smem + OFF_XS);
    float* Bs = (float*)(smem + OFF_BS);
    float* As = (float*)(smem + OFF_AS);
    float* kg = (float*)(smem + OFF_KG);

    const int tid  = threadIdx.x;
    const int wid  = tid >> 5;
    const int bz   = blockIdx.z;
    const int bimg = bz >> 1;
    const int half = bz & 1;
    const int h0   = blockIdx.y * 16;
    const int w0   = blockIdx.x * 16;
    const int pr = tid >> 4, pc = tid & 15;

    const int warp_m = wid >> 2;
    const int warp_n = wid & 3;

    const float* ysrc = g_y + bimg * (CO * HO * WO);

    // load gaussian weights for this tile
#pragma unroll
    for (int t = 0; t < 9; ++t)
        kg[t * 256 + tid] = g_k[((bimg * 9 + t) * HO + h0 + pr) * WO + w0 + pc];
    __syncthreads();

    FragC cf[2][4];
#pragma unroll
    for (int i = 0; i < 2; ++i)
#pragma unroll
        for (int j = 0; j < 4; ++j) wmma::fill_fragment(cf[i][j], 0.f);

    for (int cc = 0; cc < 5; ++cc) {          // 4 c-blocks + 1 bias pass
        const bool bias_pass = (cc == 4);
        if (!bias_pass) {
            __syncthreads();
            for (int e = tid; e < 32 * 342; e += 256) {
                int c = e / 342;
                int rem = e - c * 342;
                int r = rem / 19, s = rem - r * 19;
                int yh = h0 - 1 + r, yw = w0 - 1 + s;
                float v = 0.f;
                if ((unsigned)yh < 128u && (unsigned)yw < 128u)
                    v = ysrc[((cc * 32 + c) * HO + yh) * WO + yw];
                ys[e] = v;
            }
            __syncthreads();
        }

        const int ntap = bias_pass ? 1 : 9;
        for (int tap = 0; tap < ntap; ++tap) {
            const int chunk = bias_pass ? 36 : cc * 9 + tap;
            // A tile: 64 x 32, pitch 36
            {
                const float4* asrc = (const float4*)(g_w2a + (chunk * CO + half * 64) * 32);
#pragma unroll
                for (int q = 0; q < 2; ++q) {
                    int idx = tid + q * 256;
                    int row = idx >> 3, kb = idx & 7;
                    *(float4*)(As + row * 36 + kb * 4) = asrc[idx];
                }
            }
            // B tile: 32 x 256, pitch 260
            if (bias_pass) {
#pragma unroll
                for (int kk = 0; kk < 32; ++kk)
                    Bs[kk * 260 + tid] = (kk == 0) ? 1.f : 0.f;
            } else {
                const int ti = tap / 3, tj = tap - ti * 3;
                const float kgv = kg[tap * 256 + tid];
                const float* yb = ys + (pr + ti) * 19 + (pc + tj);
#pragma unroll
                for (int kk = 0; kk < 32; ++kk)
                    Bs[kk * 260 + tid] = tf32r(yb[kk * 342] * kgv);
            }
            __syncthreads();

#pragma unroll
            for (int ks = 0; ks < 4; ++ks) {
                FragA af[2];
                FragB bf[4];
#pragma unroll
                for (int i = 0; i < 2; ++i)
                    wmma::load_matrix_sync(af[i], As + (warp_m * 32 + i * 16) * 36 + ks * 8, 36);
#pragma unroll
                for (int j = 0; j < 4; ++j)
                    wmma::load_matrix_sync(bf[j], Bs + ks * 8 * 260 + warp_n * 64 + j * 16, 260);
#pragma unroll
                for (int i = 0; i < 2; ++i)
#pragma unroll
                    for (int j = 0; j < 4; ++j)
                        wmma::mma_sync(cf[i][j], af[i], bf[j], cf[i][j]);
            }
            __syncthreads();
        }
    }

    // Epilogue: each 16-col fragment = one contiguous 16-px row segment
    const int m0 = half * 64 + warp_m * 32;
#pragma unroll
    for (int i = 0; i < 2; ++i)
#pragma unroll
        for (int j = 0; j < 4; ++j) {
            int q = warp_n * 4 + j;           // pixel row within tile (0..15)
            float* dst = out + ((bimg * CO + m0 + i * 16) * HO + h0 + q) * WO + w0;
            wmma::store_matrix_sync(dst, cf[i][j], HO * WO, wmma::mem_row_major);
        }
}

// ===========================================================================
extern "C" void kernel_launch(void* const* d_in, const int* in_sizes, int n_in,
                              void* d_out, int out_size) {
    const float* x     = (const float*)d_in[0];
    const float* guide = (const float*)d_in[1];
    const float* w1    = (const float*)d_in[2];
    const float* b1    = (const float*)d_in[3];
    const float* w2    = (const float*)d_in[4];
    const float* b2    = (const float*)d_in[5];
    float* out = (float*)d_out;

    static int configured = 0;
    if (!configured) {
        cudaFuncSetAttribute(deconv_wmma, cudaFuncAttributeMaxDynamicSharedMemorySize, SMEM_DC);
        cudaFuncSetAttribute(pac_wmma, cudaFuncAttributeMaxDynamicSharedMemorySize, SMEM_PAC);
        configured = 1;
    }

    prep_w1a_kernel<<<528, 256>>>(w1, b1);
    prep_w2a_kernel<<<296, 256>>>(w2, b2);
    gauss_kernel<<<dim3(8, 8, 4), 256>>>(guide);
    deconv_wmma<<<dim3(4, 4, 32), 256, SMEM_DC>>>(x);
    pac_wmma<<<dim3(8, 8, 8), 256, SMEM_PAC>>>(out);
}

// round 12
// speedup vs baseline: 1.7204x; 1.0209x over previous
#include <cuda_runtime.h>
#include <mma.h>
#include <cstdint>

using namespace nvcuda;

#define B_   4
#define CIN  256
#define CO   128
#define HI   64
#define WI   64
#define HO   128
#define WO   128

// Scratch buffers
__device__ float g_y[B_ * CO * HO * WO];      // deconv output (incl. bias)
__device__ float g_k[B_ * 9 * HO * WO];       // gaussian PAC weights
__device__ float g_w1a[4 * 33 * CO * 32];     // [par][chunk][o][kk], tf32; chunk32=bias
__device__ float g_w2a[37 * CO * 32];         // [chunk][o][kk], tf32; chunk36=bias

__device__ __forceinline__ float tf32r(float v) {
    float r;
    asm("cvt.rna.tf32.f32 %0, %1;" : "=f"(r) : "f"(v));
    return r;
}

// ===================== Weight prep =====================
__global__ void prep_w1a_kernel(const float* __restrict__ w1,
                                const float* __restrict__ b1) {
    int idx = blockIdx.x * blockDim.x + threadIdx.x;
    const int total = 4 * 33 * CO * 32;
    for (; idx < total; idx += gridDim.x * blockDim.x) {
        int kk    = idx & 31;
        int o     = (idx >> 5) & 127;
        int rem   = idx >> 12;          // par*33 + chunk
        int par   = rem / 33;
        int chunk = rem - par * 33;
        float v;
        if (chunk == 32) {
            v = (kk == 0) ? b1[o] : 0.f;
        } else {
            int cc = chunk >> 2, tap = chunk & 3;
            int c  = cc * 32 + kk;
            int ph = par >> 1, pw = par & 1;
            int a  = tap >> 1, bb = tap & 1;
            int kh = 2 * a + 1 - ph;
            int kw = 2 * bb + 1 - pw;
            v = w1[((c * CO + o) * 4 + kh) * 4 + kw];
        }
        g_w1a[idx] = tf32r(v);
    }
}

__global__ void prep_w2a_kernel(const float* __restrict__ w2,
                                const float* __restrict__ b2) {
    int idx = blockIdx.x * blockDim.x + threadIdx.x;
    const int total = 37 * CO * 32;
    for (; idx < total; idx += gridDim.x * blockDim.x) {
        int kk    = idx & 31;
        int o     = (idx >> 5) & 127;
        int chunk = idx >> 12;
        float v;
        if (chunk == 36) {
            v = (kk == 0) ? b2[o] : 0.f;
        } else {
            int cc = chunk / 9, tap = chunk - cc * 9;
            int c  = cc * 32 + kk;
            int i = tap / 3, j = tap - i * 3;
            v = w2[(c * CO + o) * 9 + (2 - i) * 3 + (2 - j)];
        }
        g_w2a[idx] = tf32r(v);
    }
}

// ===================== Gaussian kernel weights ==========
__global__ __launch_bounds__(256) void gauss_kernel(const float* __restrict__ guide) {
    __shared__ float gs[8 * 342];   // [c][r*19+s], pitch 19, 18 rows

    const int tid  = threadIdx.x;
    const int bimg = blockIdx.z;
    const int h0   = blockIdx.y * 16;
    const int w0   = blockIdx.x * 16;
    const int pr = tid >> 4, pc = tid & 15;

    const float* gsrc = guide + bimg * (CO * HO * WO);

    float ssd[9];
#pragma unroll
    for (int t = 0; t < 9; ++t) ssd[t] = 0.f;

    for (int c0 = 0; c0 < CO; c0 += 8) {
        for (int e = tid; e < 8 * 342; e += 256) {
            int c = e / 342;
            int rem = e - c * 342;
            int r = rem / 19, s = rem - r * 19;
            int gh = h0 - 1 + r, gw = w0 - 1 + s;
            float v = 0.f;
            if ((unsigned)gh < 128u && (unsigned)gw < 128u)
                v = gsrc[((c0 + c) * HO + gh) * WO + gw];
            gs[e] = v;
        }
        __syncthreads();
#pragma unroll
        for (int t = 0; t < 9; ++t) {
            const int ti = t / 3, tj = t - ti * 3;
            float s_ = ssd[t];
#pragma unroll
            for (int c = 0; c < 8; ++c) {
                float ctr = gs[c * 342 + (pr + 1) * 19 + (pc + 1)];
                float nb  = gs[c * 342 + (pr + ti) * 19 + (pc + tj)];
                float d = nb - ctr;
                s_ = fmaf(d, d, s_);
            }
            ssd[t] = s_;
        }
        __syncthreads();
    }
#pragma unroll
    for (int t = 0; t < 9; ++t)
        g_k[((bimg * 9 + t) * HO + h0 + pr) * WO + w0 + pc] = __expf(-0.5f * ssd[t]);
}

// ===================== WMMA fragments ==============
typedef wmma::fragment<wmma::matrix_a, 16, 16, 8, wmma::precision::tf32, wmma::row_major> FragA;
typedef wmma::fragment<wmma::matrix_b, 16, 16, 8, wmma::precision::tf32, wmma::row_major> FragB;
typedef wmma::fragment<wmma::accumulator, 16, 16, 8, float> FragC;

// smem float offsets
// halo: 32ch x 10rows x pitch19 = 6080 floats
// Bs:   32 x pitch132            = 4224 floats
// As:   128 x pitch36            = 4608 floats
// kg (pac only): 9 x 128         = 1152 floats
#define HALO_F 0
#define BS_F   6080
#define AS_F   10304
#define KG_F   14912
#define SMEM_DC_B  59648
#define SMEM_PAC_B 64256
#define CS_PITCH   132

// ===================== Stage 1: deconv via WMMA tf32 (M=128, N=128) =========
__global__ __launch_bounds__(256) void deconv_wmma(const float* __restrict__ x) {
    extern __shared__ float smf[];
    float* xs = smf + HALO_F;
    float* Bs = smf + BS_F;
    float* As = smf + AS_F;

    const int tid  = threadIdx.x;
    const int wid  = tid >> 5;
    const int bz   = blockIdx.z;
    const int bimg = bz >> 2;
    const int par  = bz & 3;
    const int ph = par >> 1, pw = par & 1;
    const int th0 = blockIdx.y * 8;    // parity-grid coords (0..63)
    const int tw0 = blockIdx.x * 16;

    const int warp_m = wid >> 1;       // 0..3 -> rows warp_m*32
    const int warp_n = wid & 1;        // 0..1 -> cols warp_n*64

    const int kk  = tid >> 3;          // B-build: thread owns (kk, seg)
    const int seg = tid & 7;

    const int base_h = th0 - 1 + ph;
    const int base_w = tw0 - 1 + pw;
    const float* xsrc = x + bimg * (CIN * HI * WI);
    const float* wbase = g_w1a + par * (33 * CO * 32);

    FragC cf[2][4];
#pragma unroll
    for (int i = 0; i < 2; ++i)
#pragma unroll
        for (int j = 0; j < 4; ++j) wmma::fill_fragment(cf[i][j], 0.f);

    for (int cc = 0; cc < 9; ++cc) {          // 8 c-blocks + 1 bias pass
        const bool bias_pass = (cc == 8);
        if (!bias_pass) {
            for (int e = tid; e < 32 * 190; e += 256) {
                int c = e / 190;
                int rem = e - c * 190;
                int r = rem / 19, s = rem - r * 19;
                int ih = base_h + r, iw = base_w + s;
                float v = 0.f;
                if ((unsigned)ih < 64u && (unsigned)iw < 64u)
                    v = xsrc[((cc * 32 + c) * HI + ih) * WI + iw];
                xs[e] = v;
            }
        }
        __syncthreads();

        const int ntap = bias_pass ? 1 : 4;
        for (int tap = 0; tap < ntap; ++tap) {
            const int chunk = bias_pass ? 32 : cc * 4 + tap;
            // A tile: 128 x 32, pitch 36
            {
                const float4* asrc = (const float4*)(wbase + chunk * (CO * 32));
#pragma unroll
                for (int q = 0; q < 4; ++q) {
                    int idx = tid + q * 256;          // 0..1023
                    int row = idx >> 3, kb = idx & 7;
                    *(float4*)(As + row * 36 + kb * 4) = asrc[idx];
                }
            }
            // B tile: 32 x 128, pitch 132; thread owns row kk, segment seg (16 px)
            {
                float b[16];
                if (bias_pass) {
                    float v = (kk == 0) ? 1.f : 0.f;
#pragma unroll
                    for (int i = 0; i < 16; ++i) b[i] = v;
                } else {
                    const int a = tap >> 1, bb = tap & 1;
                    const float* xrow = xs + kk * 190 + (seg + 1 - a) * 19 + (1 - bb);
#pragma unroll
                    for (int i = 0; i < 16; ++i) b[i] = tf32r(xrow[i]);
                }
                float* dst = Bs + kk * 132 + seg * 16;
#pragma unroll
                for (int q = 0; q < 4; ++q)
                    *(float4*)(dst + q * 4) = make_float4(b[q*4], b[q*4+1], b[q*4+2], b[q*4+3]);
            }
            __syncthreads();

#pragma unroll
            for (int ks = 0; ks < 4; ++ks) {
                FragA af[2];
                FragB bf[4];
#pragma unroll
                for (int i = 0; i < 2; ++i)
                    wmma::load_matrix_sync(af[i], As + (warp_m * 32 + i * 16) * 36 + ks * 8, 36);
#pragma unroll
                for (int j = 0; j < 4; ++j)
                    wmma::load_matrix_sync(bf[j], Bs + ks * 8 * 132 + warp_n * 64 + j * 16, 132);
#pragma unroll
                for (int i = 0; i < 2; ++i)
#pragma unroll
                    for (int j = 0; j < 4; ++j)
                        wmma::mma_sync(cf[i][j], af[i], bf[j], cf[i][j]);
            }
            __syncthreads();
        }
    }

    // Epilogue: two passes of 64 o-rows through smem, stride-2 scatter to g_y
    float* Cs = smf;   // 64 x 132
#pragma unroll 1
    for (int p = 0; p < 2; ++p) {
        if ((warp_m >> 1) == p) {
#pragma unroll
            for (int i = 0; i < 2; ++i)
#pragma unroll
                for (int j = 0; j < 4; ++j)
                    wmma::store_matrix_sync(Cs + ((warp_m & 1) * 32 + i * 16) * CS_PITCH +
                                            warp_n * 64 + j * 16,
                                            cf[i][j], CS_PITCH, wmma::mem_row_major);
        }
        __syncthreads();
#pragma unroll 4
        for (int t = 0; t < 32; ++t) {
            int idx = tid + t * 256;
            int ol = idx >> 7, px = idx & 127;
            int pr = px >> 4, pc = px & 15;
            int oh = 2 * (th0 + pr) + ph;
            int ow = 2 * (tw0 + pc) + pw;
            g_y[((bimg * CO + p * 64 + ol) * HO + oh) * WO + ow] = Cs[ol * CS_PITCH + px];
        }
        __syncthreads();
    }
}

// ===================== Stage 2: PAC via WMMA tf32 (M=128, N=128) ============
__global__ __launch_bounds__(256) void pac_wmma(float* __restrict__ out) {
    extern __shared__ float smf[];
    float* ys = smf + HALO_F;
    float* Bs = smf + BS_F;
    float* As = smf + AS_F;
    float* kg = smf + KG_F;

    const int tid  = threadIdx.x;
    const int wid  = tid >> 5;
    const int bimg = blockIdx.z;
    const int h0   = blockIdx.y * 8;
    const int w0   = blockIdx.x * 16;

    const int warp_m = wid >> 1;
    const int warp_n = wid & 1;

    const int kk  = tid >> 3;
    const int seg = tid & 7;

    const float* ysrc = g_y + bimg * (CO * HO * WO);

    // load gaussian weights for this tile: kg[t][px], px = pr*16+pc
    for (int idx = tid; idx < 9 * 128; idx += 256) {
        int t = idx >> 7, px = idx & 127;
        kg[idx] = g_k[((bimg * 9 + t) * HO + h0 + (px >> 4)) * WO + w0 + (px & 15)];
    }

    FragC cf[2][4];
#pragma unroll
    for (int i = 0; i < 2; ++i)
#pragma unroll
        for (int j = 0; j < 4; ++j) wmma::fill_fragment(cf[i][j], 0.f);

    for (int cc = 0; cc < 5; ++cc) {          // 4 c-blocks + 1 bias pass
        const bool bias_pass = (cc == 4);
        if (!bias_pass) {
            __syncthreads();
            for (int e = tid; e < 32 * 190; e += 256) {
                int c = e / 190;
                int rem = e - c * 190;
                int r = rem / 19, s = rem - r * 19;
                int yh = h0 - 1 + r, yw = w0 - 1 + s;
                float v = 0.f;
                if ((unsigned)yh < 128u && (unsigned)yw < 128u)
                    v = ysrc[((cc * 32 + c) * HO + yh) * WO + yw];
                ys[e] = v;
            }
        }
        __syncthreads();

        const int ntap = bias_pass ? 1 : 9;
        for (int tap = 0; tap < ntap; ++tap) {
            const int chunk = bias_pass ? 36 : cc * 9 + tap;
            // A tile: 128 x 32, pitch 36
            {
                const float4* asrc = (const float4*)(g_w2a + chunk * (CO * 32));
#pragma unroll
                for (int q = 0; q < 4; ++q) {
                    int idx = tid + q * 256;
                    int row = idx >> 3, kb = idx & 7;
                    *(float4*)(As + row * 36 + kb * 4) = asrc[idx];
                }
            }
            // B tile: 32 x 128, pitch 132
            {
                float b[16];
                if (bias_pass) {
                    float v = (kk == 0) ? 1.f : 0.f;
#pragma unroll
                    for (int i = 0; i < 16; ++i) b[i] = v;
                } else {
                    const int ti = tap / 3, tj = tap - ti * 3;
                    const float* yrow = ys + kk * 190 + (seg + ti) * 19 + tj;
                    const float* krow = kg + tap * 128 + seg * 16;
#pragma unroll
                    for (int q = 0; q < 4; ++q) {
                        float4 kv = *(const float4*)(krow + q * 4);
                        b[q*4+0] = tf32r(yrow[q*4+0] * kv.x);
                        b[q*4+1] = tf32r(yrow[q*4+1] * kv.y);
                        b[q*4+2] = tf32r(yrow[q*4+2] * kv.z);
                        b[q*4+3] = tf32r(yrow[q*4+3] * kv.w);
                    }
                }
                float* dst = Bs + kk * 132 + seg * 16;
#pragma unroll
                for (int q = 0; q < 4; ++q)
                    *(float4*)(dst + q * 4) = make_float4(b[q*4], b[q*4+1], b[q*4+2], b[q*4+3]);
            }
            __syncthreads();

#pragma unroll
            for (int ks = 0; ks < 4; ++ks) {
                FragA af[2];
                FragB bf[4];
#pragma unroll
                for (int i = 0; i < 2; ++i)
                    wmma::load_matrix_sync(af[i], As + (warp_m * 32 + i * 16) * 36 + ks * 8, 36);
#pragma unroll
                for (int j = 0; j < 4; ++j)
                    wmma::load_matrix_sync(bf[j], Bs + ks * 8 * 132 + warp_n * 64 + j * 16, 132);
#pragma unroll
                for (int i = 0; i < 2; ++i)
#pragma unroll
                    for (int j = 0; j < 4; ++j)
                        wmma::mma_sync(cf[i][j], af[i], bf[j], cf[i][j]);
            }
            __syncthreads();
        }
    }

    // Epilogue: fragment (i,j) covers o rows [warp_m*32+i*16, +16), px row seg=warp_n*4+j
    const int m0 = warp_m * 32;
#pragma unroll
    for (int i = 0; i < 2; ++i)
#pragma unroll
        for (int j = 0; j < 4; ++j) {
            int q = warp_n * 4 + j;           // pixel row within tile (0..7)
            float* dst = out + ((bimg * CO + m0 + i * 16) * HO + h0 + q) * WO + w0;
            wmma::store_matrix_sync(dst, cf[i][j], HO * WO, wmma::mem_row_major);
        }
}

// ===========================================================================
extern "C" void kernel_launch(void* const* d_in, const int* in_sizes, int n_in,
                              void* d_out, int out_size) {
    const float* x     = (const float*)d_in[0];
    const float* guide = (const float*)d_in[1];
    const float* w1    = (const float*)d_in[2];
    const float* b1    = (const float*)d_in[3];
    const float* w2    = (const float*)d_in[4];
    const float* b2    = (const float*)d_in[5];
    float* out = (float*)d_out;

    static int configured = 0;
    if (!configured) {
        cudaFuncSetAttribute(deconv_wmma, cudaFuncAttributeMaxDynamicSharedMemorySize, SMEM_DC_B);
        cudaFuncSetAttribute(pac_wmma, cudaFuncAttributeMaxDynamicSharedMemorySize, SMEM_PAC_B);
        configured = 1;
    }

    prep_w1a_kernel<<<528, 256>>>(w1, b1);
    prep_w2a_kernel<<<296, 256>>>(w2, b2);
    gauss_kernel<<<dim3(8, 8, 4), 256>>>(guide);
    deconv_wmma<<<dim3(4, 8, 16), 256, SMEM_DC_B>>>(x);
    pac_wmma<<<dim3(8, 16, 4), 256, SMEM_PAC_B>>>(out);
}